// round 7
// baseline (speedup 1.0000x reference)
#include <cuda_runtime.h>
#include <cuda_bf16.h>
#include <math.h>

// Problem constants
#define BB   4
#define TT   1024
#define DD   1024
#define HH   16
#define HD   64
#define D3   3072   // 3*D
#define MTOT 4096   // B*T

// Scratch (allocation-free rule: __device__ globals)
__device__ float g_qkv[(size_t)BB * TT * D3];   // 48 MB: [b*T+t][3D]
__device__ float g_att[(size_t)BB * TT * DD];   // 16 MB: [b*T+t][D]

// ---------------------------------------------------------------------------
// Classic SIMT fp32 GEMM: C[M,N] = A[M,K] @ B[K,N], all row-major.
// BM=BN=128, BK=8, 256 threads, 8x8 per-thread microtile, float4 everywhere.
// Requires M%128==0, N%128==0, K%8==0 (true for all three GEMM shapes here).
// ---------------------------------------------------------------------------
__global__ __launch_bounds__(256, 2)
void sgemm128(const float* __restrict__ A, const float* __restrict__ B,
              float* __restrict__ C, int M, int N, int K)
{
    __shared__ float As[8 * 132];   // [k][m], padded pitch 132
    __shared__ float Bs[8 * 132];   // [k][n], padded pitch 132

    const int tid  = threadIdx.x;
    const int cRow = blockIdx.y;
    const int cCol = blockIdx.x;

    // A tile loader: 128x8 -> 256 float4 loads (1 per thread), store transposed
    const int irA = tid >> 1;            // 0..127
    const int icA = (tid & 1) << 2;      // 0 or 4
    // B tile loader: 8x128 -> 256 float4 loads
    const int irB = tid >> 5;            // 0..7
    const int icB = (tid & 31) << 2;     // 0..124

    const int tr  = tid >> 4;            // 0..15 -> rows tr*8..+8
    const int tcc = tid & 15;            // 0..15 -> cols tcc*8..+8

    const float* Ab = A + (size_t)(cRow * 128 + irA) * K + icA;
    const float* Bb = B + (size_t)irB * N + cCol * 128 + icB;

    float acc[8][8];
#pragma unroll
    for (int i = 0; i < 8; i++)
#pragma unroll
        for (int j = 0; j < 8; j++) acc[i][j] = 0.0f;

    for (int kt = 0; kt < K; kt += 8) {
        const float4 av = *reinterpret_cast<const float4*>(Ab + kt);
        const float4 bv = *reinterpret_cast<const float4*>(Bb + (size_t)kt * N);

        As[(icA + 0) * 132 + irA] = av.x;
        As[(icA + 1) * 132 + irA] = av.y;
        As[(icA + 2) * 132 + irA] = av.z;
        As[(icA + 3) * 132 + irA] = av.w;
        *reinterpret_cast<float4*>(Bs + irB * 132 + icB) = bv;

        __syncthreads();

#pragma unroll
        for (int k = 0; k < 8; k++) {
            float ra[8], rb[8];
            *reinterpret_cast<float4*>(ra)     = *reinterpret_cast<const float4*>(As + k * 132 + tr * 8);
            *reinterpret_cast<float4*>(ra + 4) = *reinterpret_cast<const float4*>(As + k * 132 + tr * 8 + 4);
            *reinterpret_cast<float4*>(rb)     = *reinterpret_cast<const float4*>(Bs + k * 132 + tcc * 8);
            *reinterpret_cast<float4*>(rb + 4) = *reinterpret_cast<const float4*>(Bs + k * 132 + tcc * 8 + 4);
#pragma unroll
            for (int i = 0; i < 8; i++)
#pragma unroll
                for (int j = 0; j < 8; j++)
                    acc[i][j] = fmaf(ra[i], rb[j], acc[i][j]);
        }
        __syncthreads();
    }

    float* Cb = C + (size_t)(cRow * 128 + tr * 8) * N + cCol * 128 + tcc * 8;
#pragma unroll
    for (int i = 0; i < 8; i++) {
        float4 v0 = make_float4(acc[i][0], acc[i][1], acc[i][2], acc[i][3]);
        float4 v1 = make_float4(acc[i][4], acc[i][5], acc[i][6], acc[i][7]);
        *reinterpret_cast<float4*>(Cb + (size_t)i * N)     = v0;
        *reinterpret_cast<float4*>(Cb + (size_t)i * N + 4) = v1;
    }
}

// ---------------------------------------------------------------------------
// Flash attention (causal), fp32. One CTA handles a 64-query block for one
// (b,h). 256 threads = 64 rows x 4 thread-cols; each thread owns 16 S columns
// (for QK^T) and 16 output head-dims (for PV). Online softmax; row reductions
// via __shfl_xor over the 4-thread group (lanes differ in bits 0,1).
// Ps exchange is intra-warp only (a row's 4 threads share a warp), so only
// the K/V tile reload needs __syncthreads.
// ---------------------------------------------------------------------------
#define APITCH 68                       // padded float pitch for 64-wide tiles
#define ATT_SMEM (4 * 64 * APITCH * 4)  // Qs,Ks,Vs,Ps = 69632 bytes

__global__ __launch_bounds__(256, 2)
void attn_kernel(const float* __restrict__ qkv, float* __restrict__ att)
{
    extern __shared__ float sm[];
    float* Qs = sm;
    float* Ks = Qs + 64 * APITCH;
    float* Vs = Ks + 64 * APITCH;
    float* Ps = Vs + 64 * APITCH;

    const int tid = threadIdx.x;
    const int r   = tid >> 2;      // 0..63 : row within Q block
    const int tc  = tid & 3;       // 0..3  : column group

    const int bh = blockIdx.y;
    const int b  = bh >> 4;
    const int h  = bh & 15;
    const int q0 = blockIdx.x * 64;

    const float* base = qkv + (size_t)b * TT * D3 + h * HD;

    // Load Q block (scaled by 1/sqrt(HD) = 0.125)
    {
        const float4* g  = reinterpret_cast<const float4*>(base + (size_t)(q0 + r) * D3 + tc * 16);
        float4*       s4 = reinterpret_cast<float4*>(Qs + r * APITCH + tc * 16);
#pragma unroll
        for (int i = 0; i < 4; i++) {
            float4 v = g[i];
            v.x *= 0.125f; v.y *= 0.125f; v.z *= 0.125f; v.w *= 0.125f;
            s4[i] = v;
        }
    }

    float o[16];
#pragma unroll
    for (int i = 0; i < 16; i++) o[i] = 0.0f;
    float m = -INFINITY, l = 0.0f;

    const int ntiles = blockIdx.x + 1;   // causal: only tiles with kv0 <= q0+63

    for (int kt = 0; kt < ntiles; ++kt) {
        __syncthreads();  // previous tile's Ks/Vs reads done
        {
            const float* krow = base + 1024 + (size_t)(kt * 64 + r) * D3 + tc * 16;
            const float* vrow = krow + 1024;
            float4* ks4 = reinterpret_cast<float4*>(Ks + r * APITCH + tc * 16);
            float4* vs4 = reinterpret_cast<float4*>(Vs + r * APITCH + tc * 16);
#pragma unroll
            for (int i = 0; i < 4; i++) {
                ks4[i] = reinterpret_cast<const float4*>(krow)[i];
                vs4[i] = reinterpret_cast<const float4*>(vrow)[i];
            }
        }
        __syncthreads();

        // S = (Q/8) @ K^T for this thread's 16 columns
        float s[16];
#pragma unroll
        for (int j = 0; j < 16; j++) s[j] = 0.0f;

        const float4* q4 = reinterpret_cast<const float4*>(Qs + r * APITCH);
#pragma unroll
        for (int d4 = 0; d4 < 16; ++d4) {
            const float4 qv = q4[d4];
#pragma unroll
            for (int j = 0; j < 16; ++j) {
                const float4 kv = *reinterpret_cast<const float4*>(Ks + (tc * 16 + j) * APITCH + d4 * 4);
                s[j] = fmaf(qv.x, kv.x, s[j]);
                s[j] = fmaf(qv.y, kv.y, s[j]);
                s[j] = fmaf(qv.z, kv.z, s[j]);
                s[j] = fmaf(qv.w, kv.w, s[j]);
            }
        }

        // Causal mask only on the diagonal tile (kv_local > q_local)
        if (kt == blockIdx.x) {
#pragma unroll
            for (int j = 0; j < 16; j++)
                if (tc * 16 + j > r) s[j] = -INFINITY;
        }

        // Online softmax
        float mt = s[0];
#pragma unroll
        for (int j = 1; j < 16; j++) mt = fmaxf(mt, s[j]);
        mt = fmaxf(mt, __shfl_xor_sync(0xffffffffu, mt, 1));
        mt = fmaxf(mt, __shfl_xor_sync(0xffffffffu, mt, 2));

        const float mn   = fmaxf(m, mt);       // finite after first tile (diag always valid)
        const float corr = __expf(m - mn);     // m=-inf first time -> 0
        float ls = 0.0f;
#pragma unroll
        for (int j = 0; j < 16; j++) {
            const float p = __expf(s[j] - mn);
            Ps[r * APITCH + tc * 16 + j] = p;
            ls += p;
        }
        ls += __shfl_xor_sync(0xffffffffu, ls, 1);
        ls += __shfl_xor_sync(0xffffffffu, ls, 2);
        l = l * corr + ls;
        m = mn;
#pragma unroll
        for (int i = 0; i < 16; i++) o[i] *= corr;

        __syncwarp();  // P exchange is within the row's 4-thread group (same warp)

        // O += P @ V for this thread's 16 head-dims
#pragma unroll 4
        for (int jj = 0; jj < 64; ++jj) {
            const float  p  = Ps[r * APITCH + jj];
            const float* vb = Vs + jj * APITCH + tc * 16;
            const float4 v0 = *reinterpret_cast<const float4*>(vb);
            const float4 v1 = *reinterpret_cast<const float4*>(vb + 4);
            const float4 v2 = *reinterpret_cast<const float4*>(vb + 8);
            const float4 v3 = *reinterpret_cast<const float4*>(vb + 12);
            o[0]  = fmaf(p, v0.x, o[0]);  o[1]  = fmaf(p, v0.y, o[1]);
            o[2]  = fmaf(p, v0.z, o[2]);  o[3]  = fmaf(p, v0.w, o[3]);
            o[4]  = fmaf(p, v1.x, o[4]);  o[5]  = fmaf(p, v1.y, o[5]);
            o[6]  = fmaf(p, v1.z, o[6]);  o[7]  = fmaf(p, v1.w, o[7]);
            o[8]  = fmaf(p, v2.x, o[8]);  o[9]  = fmaf(p, v2.y, o[9]);
            o[10] = fmaf(p, v2.z, o[10]); o[11] = fmaf(p, v2.w, o[11]);
            o[12] = fmaf(p, v3.x, o[12]); o[13] = fmaf(p, v3.y, o[13]);
            o[14] = fmaf(p, v3.z, o[14]); o[15] = fmaf(p, v3.w, o[15]);
        }
    }

    // Normalize and write [b, t, h*64 + d]
    const float inv = 1.0f / l;
    float* op = att + (size_t)(b * TT + q0 + r) * DD + h * HD + tc * 16;
#pragma unroll
    for (int i4 = 0; i4 < 4; i4++) {
        float4 v = make_float4(o[i4 * 4 + 0] * inv, o[i4 * 4 + 1] * inv,
                               o[i4 * 4 + 2] * inv, o[i4 * 4 + 3] * inv);
        *reinterpret_cast<float4*>(op + i4 * 4) = v;
    }
}

// ---------------------------------------------------------------------------
// Launch: qkv GEMM -> flash attention -> output GEMM (all default stream,
// graph-capturable; no allocation, no sync).
// Input order per metadata: x[f32], mask[i32, ignored: it is exactly triu(k=1)],
// w_qkv[f32], w_out[f32]. Output: f32 [B,T,D].
// ---------------------------------------------------------------------------
extern "C" void kernel_launch(void* const* d_in, const int* in_sizes, int n_in,
                              void* d_out, int out_size)
{
    const float* x     = (const float*)d_in[0];
    const float* w_qkv = (const float*)d_in[2];
    const float* w_out = (const float*)d_in[3];
    float*       out   = (float*)d_out;

    float* qkv_p = nullptr;
    float* att_p = nullptr;
    cudaGetSymbolAddress((void**)&qkv_p, g_qkv);
    cudaGetSymbolAddress((void**)&att_p, g_att);

    cudaFuncSetAttribute(attn_kernel,
                         cudaFuncAttributeMaxDynamicSharedMemorySize, ATT_SMEM);

    // 1) qkv = x @ w_qkv : [4096,1024] @ [1024,3072]
    sgemm128<<<dim3(D3 / 128, MTOT / 128), 256>>>(x, w_qkv, qkv_p, MTOT, D3, DD);

    // 2) causal flash attention over 64 (b,h) pairs, 16 q-blocks each
    attn_kernel<<<dim3(TT / 64, BB * HH), 256, ATT_SMEM>>>(qkv_p, att_p);

    // 3) out = att @ w_out : [4096,1024] @ [1024,1024]
    sgemm128<<<dim3(DD / 128, MTOT / 128), 256>>>(att_p, w_out, out, MTOT, DD, DD);
}

// round 9
// speedup vs baseline: 2.1555x; 2.1555x over previous
#include <cuda_runtime.h>
#include <cuda_bf16.h>
#include <math.h>

// Problem constants
#define BB   4
#define TT   1024
#define DD   1024
#define HH   16
#define HD   64
#define D3   3072   // 3*D
#define MTOT 4096   // B*T

// Scratch (allocation-free rule: __device__ globals)
__device__ float g_qkv[(size_t)BB * TT * D3];   // 48 MB: [b*T+t][3D]
__device__ float g_att[(size_t)BB * TT * DD];   // 16 MB: [b*T+t][D]

// ---------------------------------------------------------------------------
// Classic SIMT fp32 GEMM: C[M,N] = A[M,K] @ B[K,N], all row-major.
// BM=BN=128, BK=8, 256 threads, 8x8 per-thread microtile, float4 everywhere.
// ---------------------------------------------------------------------------
__global__ __launch_bounds__(256, 2)
void sgemm128(const float* __restrict__ A, const float* __restrict__ B,
              float* __restrict__ C, int M, int N, int K)
{
    __shared__ float As[8 * 132];   // [k][m], padded pitch 132
    __shared__ float Bs[8 * 132];   // [k][n], padded pitch 132

    const int tid  = threadIdx.x;
    const int cRow = blockIdx.y;
    const int cCol = blockIdx.x;

    const int irA = tid >> 1;            // 0..127
    const int icA = (tid & 1) << 2;      // 0 or 4
    const int irB = tid >> 5;            // 0..7
    const int icB = (tid & 31) << 2;     // 0..124

    const int tr  = tid >> 4;            // 0..15
    const int tcc = tid & 15;            // 0..15

    const float* Ab = A + (size_t)(cRow * 128 + irA) * K + icA;
    const float* Bb = B + (size_t)irB * N + cCol * 128 + icB;

    float acc[8][8];
#pragma unroll
    for (int i = 0; i < 8; i++)
#pragma unroll
        for (int j = 0; j < 8; j++) acc[i][j] = 0.0f;

    for (int kt = 0; kt < K; kt += 8) {
        const float4 av = *reinterpret_cast<const float4*>(Ab + kt);
        const float4 bv = *reinterpret_cast<const float4*>(Bb + (size_t)kt * N);

        As[(icA + 0) * 132 + irA] = av.x;
        As[(icA + 1) * 132 + irA] = av.y;
        As[(icA + 2) * 132 + irA] = av.z;
        As[(icA + 3) * 132 + irA] = av.w;
        *reinterpret_cast<float4*>(Bs + irB * 132 + icB) = bv;

        __syncthreads();

#pragma unroll
        for (int k = 0; k < 8; k++) {
            float ra[8], rb[8];
            *reinterpret_cast<float4*>(ra)     = *reinterpret_cast<const float4*>(As + k * 132 + tr * 8);
            *reinterpret_cast<float4*>(ra + 4) = *reinterpret_cast<const float4*>(As + k * 132 + tr * 8 + 4);
            *reinterpret_cast<float4*>(rb)     = *reinterpret_cast<const float4*>(Bs + k * 132 + tcc * 8);
            *reinterpret_cast<float4*>(rb + 4) = *reinterpret_cast<const float4*>(Bs + k * 132 + tcc * 8 + 4);
#pragma unroll
            for (int i = 0; i < 8; i++)
#pragma unroll
                for (int j = 0; j < 8; j++)
                    acc[i][j] = fmaf(ra[i], rb[j], acc[i][j]);
        }
        __syncthreads();
    }

    float* Cb = C + (size_t)(cRow * 128 + tr * 8) * N + cCol * 128 + tcc * 8;
#pragma unroll
    for (int i = 0; i < 8; i++) {
        float4 v0 = make_float4(acc[i][0], acc[i][1], acc[i][2], acc[i][3]);
        float4 v1 = make_float4(acc[i][4], acc[i][5], acc[i][6], acc[i][7]);
        *reinterpret_cast<float4*>(Cb + (size_t)i * N)     = v0;
        *reinterpret_cast<float4*>(Cb + (size_t)i * N + 4) = v1;
    }
}

// ---------------------------------------------------------------------------
// Flash attention (causal), fp32, register-blocked.
// One CTA: 128 queries x one (b,h); KV tiles of 64. 256 threads = 16x16 grid,
// each thread owns an 8(row) x 4(col) microtile for BOTH S=Q@K^T and O+=P@V,
// computed as rank-1 updates (3 LDS.128 -> 32 FFMA per k-step).
// Layouts: Qs [d][row] (pitch 132), Ks [d][key] (pitch 68),
//          Vs [key][d] (pitch 68),  Ps [key][row] (pitch 132).
// Row softmax stats reduced across the 16-lane tc-group via shfl_xor.
// Heavy (high-tile-count) blocks scheduled first via reversed blockIdx.x.
// ---------------------------------------------------------------------------
#define QP 132
#define KP 68
#define ATT2_SMEM ((64 * QP + 64 * KP + 64 * KP + 64 * QP) * 4)  // 102400 B

__global__ __launch_bounds__(256, 2)
void attn128(const float* __restrict__ qkv, float* __restrict__ att)
{
    extern __shared__ float sm[];
    float* Qs = sm;                     // [64][QP]  d-major
    float* Ks = Qs + 64 * QP;           // [64][KP]  d-major
    float* Vs = Ks + 64 * KP;           // [64][KP]  key-major
    float* Ps = Vs + 64 * KP;           // [64][QP]  key-major

    const int tid = threadIdx.x;
    const int tr  = tid >> 4;           // 0..15 -> rows r0..r0+8
    const int tc  = tid & 15;           // 0..15 -> cols c0..c0+4
    const int r0  = tr * 8;
    const int c0  = tc * 4;

    const int bh  = blockIdx.y;
    const int b   = bh >> 4;
    const int h   = bh & 15;
    const int bxe = (int)(gridDim.x - 1) - (int)blockIdx.x;  // heavy first
    const int q0  = bxe * 128;

    const float* base = qkv + (size_t)b * TT * D3 + h * HD;

    // Load Q block transposed (scaled by 1/sqrt(HD) = 0.125): Qs[d][row]
    {
        const int lr    = tid >> 1;            // 0..127
        const int dbase = (tid & 1) * 32;
        const float* g  = base + (size_t)(q0 + lr) * D3 + dbase;
#pragma unroll
        for (int i = 0; i < 8; i++) {
            float4 v = reinterpret_cast<const float4*>(g)[i];
            const int d = dbase + i * 4;
            Qs[(d + 0) * QP + lr] = v.x * 0.125f;
            Qs[(d + 1) * QP + lr] = v.y * 0.125f;
            Qs[(d + 2) * QP + lr] = v.z * 0.125f;
            Qs[(d + 3) * QP + lr] = v.w * 0.125f;
        }
    }

    float o[8][4];
#pragma unroll
    for (int i = 0; i < 8; i++)
#pragma unroll
        for (int j = 0; j < 4; j++) o[i][j] = 0.0f;
    float mrow[8], lrow[8];
#pragma unroll
    for (int i = 0; i < 8; i++) { mrow[i] = -INFINITY; lrow[i] = 0.0f; }

    const int ntiles = 2 * bxe + 2;     // causal: tiles with kv0 <= q0+127

    for (int kt = 0; kt < ntiles; ++kt) {
        __syncthreads();   // prior S done with Ks, prior PV done with Vs/Ps

        // Load K (transposed -> Ks[d][key]) and V (natural -> Vs[key][d])
        {
            const int kr    = tid >> 2;         // 0..63
            const int dbase = (tid & 3) * 16;
            const float* kg = base + 1024 + (size_t)(kt * 64 + kr) * D3 + dbase;
            const float* vg = kg + 1024;
#pragma unroll
            for (int i = 0; i < 4; i++) {
                float4 kv = reinterpret_cast<const float4*>(kg)[i];
                const int d = dbase + i * 4;
                Ks[(d + 0) * KP + kr] = kv.x;
                Ks[(d + 1) * KP + kr] = kv.y;
                Ks[(d + 2) * KP + kr] = kv.z;
                Ks[(d + 3) * KP + kr] = kv.w;
                *reinterpret_cast<float4*>(&Vs[kr * KP + d]) =
                    reinterpret_cast<const float4*>(vg)[i];
            }
        }
        __syncthreads();

        // S microtile: s[8][4] = (Q/8) @ K^T
        float s[8][4];
#pragma unroll
        for (int i = 0; i < 8; i++)
#pragma unroll
            for (int j = 0; j < 4; j++) s[i][j] = 0.0f;

#pragma unroll 4
        for (int d = 0; d < 64; ++d) {
            float ra[8], rb[4];
            *reinterpret_cast<float4*>(ra)     = *reinterpret_cast<const float4*>(&Qs[d * QP + r0]);
            *reinterpret_cast<float4*>(ra + 4) = *reinterpret_cast<const float4*>(&Qs[d * QP + r0 + 4]);
            *reinterpret_cast<float4*>(rb)     = *reinterpret_cast<const float4*>(&Ks[d * KP + c0]);
#pragma unroll
            for (int i = 0; i < 8; i++)
#pragma unroll
                for (int j = 0; j < 4; j++)
                    s[i][j] = fmaf(ra[i], rb[j], s[i][j]);
        }

        // Causal mask (only in diagonal region: last two tiles of this block)
        const int dk = kt - 2 * bxe;
        if (dk >= 0) {
#pragma unroll
            for (int i = 0; i < 8; i++)
#pragma unroll
                for (int j = 0; j < 4; j++)
                    if (dk * 64 + c0 + j > r0 + i) s[i][j] = -INFINITY;
        }

        // Online softmax per owned row; p overwrites s[][]
#pragma unroll
        for (int i = 0; i < 8; i++) {
            float mt = fmaxf(fmaxf(s[i][0], s[i][1]), fmaxf(s[i][2], s[i][3]));
            mt = fmaxf(mt, __shfl_xor_sync(0xffffffffu, mt, 1));
            mt = fmaxf(mt, __shfl_xor_sync(0xffffffffu, mt, 2));
            mt = fmaxf(mt, __shfl_xor_sync(0xffffffffu, mt, 4));
            mt = fmaxf(mt, __shfl_xor_sync(0xffffffffu, mt, 8));

            const float mn   = fmaxf(mrow[i], mt);
            const float corr = __expf(mrow[i] - mn);
            float ls = 0.0f;
#pragma unroll
            for (int j = 0; j < 4; j++) {
                const float p = __expf(s[i][j] - mn);
                s[i][j] = p;
                ls += p;
            }
            ls += __shfl_xor_sync(0xffffffffu, ls, 1);
            ls += __shfl_xor_sync(0xffffffffu, ls, 2);
            ls += __shfl_xor_sync(0xffffffffu, ls, 4);
            ls += __shfl_xor_sync(0xffffffffu, ls, 8);
            lrow[i] = lrow[i] * corr + ls;
            mrow[i] = mn;
            o[i][0] *= corr; o[i][1] *= corr; o[i][2] *= corr; o[i][3] *= corr;
        }

        // Write P transposed (key-major) via vectorized stores: Ps[key][row]
#pragma unroll
        for (int j = 0; j < 4; j++) {
            float4 lo = make_float4(s[0][j], s[1][j], s[2][j], s[3][j]);
            float4 hi = make_float4(s[4][j], s[5][j], s[6][j], s[7][j]);
            *reinterpret_cast<float4*>(&Ps[(c0 + j) * QP + r0])     = lo;
            *reinterpret_cast<float4*>(&Ps[(c0 + j) * QP + r0 + 4]) = hi;
        }
        __syncthreads();

        // O microtile: o[8][4] += P @ V (rank-1 over keys)
#pragma unroll 4
        for (int k = 0; k < 64; ++k) {
            float pa[8], vb[4];
            *reinterpret_cast<float4*>(pa)     = *reinterpret_cast<const float4*>(&Ps[k * QP + r0]);
            *reinterpret_cast<float4*>(pa + 4) = *reinterpret_cast<const float4*>(&Ps[k * QP + r0 + 4]);
            *reinterpret_cast<float4*>(vb)     = *reinterpret_cast<const float4*>(&Vs[k * KP + c0]);
#pragma unroll
            for (int i = 0; i < 8; i++)
#pragma unroll
                for (int j = 0; j < 4; j++)
                    o[i][j] = fmaf(pa[i], vb[j], o[i][j]);
        }
    }

    // Normalize and write [b, q0+r, h*64 + d]
#pragma unroll
    for (int i = 0; i < 8; i++) {
        const float inv = 1.0f / lrow[i];
        float* op = att + (size_t)(b * TT + q0 + r0 + i) * DD + h * HD + c0;
        *reinterpret_cast<float4*>(op) =
            make_float4(o[i][0] * inv, o[i][1] * inv, o[i][2] * inv, o[i][3] * inv);
    }
}

// ---------------------------------------------------------------------------
// Launch: qkv GEMM -> flash attention -> output GEMM (graph-capturable).
// Inputs: x[f32], mask[i32, ignored: exactly triu(k=1)], w_qkv[f32], w_out[f32].
// ---------------------------------------------------------------------------
extern "C" void kernel_launch(void* const* d_in, const int* in_sizes, int n_in,
                              void* d_out, int out_size)
{
    const float* x     = (const float*)d_in[0];
    const float* w_qkv = (const float*)d_in[2];
    const float* w_out = (const float*)d_in[3];
    float*       out   = (float*)d_out;

    float* qkv_p = nullptr;
    float* att_p = nullptr;
    cudaGetSymbolAddress((void**)&qkv_p, g_qkv);
    cudaGetSymbolAddress((void**)&att_p, g_att);

    cudaFuncSetAttribute(attn128,
                         cudaFuncAttributeMaxDynamicSharedMemorySize, ATT2_SMEM);

    // 1) qkv = x @ w_qkv : [4096,1024] @ [1024,3072]
    sgemm128<<<dim3(D3 / 128, MTOT / 128), 256>>>(x, w_qkv, qkv_p, MTOT, D3, DD);

    // 2) causal flash attention: 8 q-blocks x 64 (b,h) pairs
    attn128<<<dim3(TT / 128, BB * HH), 256, ATT2_SMEM>>>(qkv_p, att_p);

    // 3) out = att @ w_out : [4096,1024] @ [1024,1024]
    sgemm128<<<dim3(DD / 128, MTOT / 128), 256>>>(att_p, w_out, out, MTOT, DD, DD);
}

// round 13
// speedup vs baseline: 3.9154x; 1.8165x over previous
#include <cuda_runtime.h>
#include <cuda_bf16.h>
#include <math.h>
#include <stdint.h>

// Problem constants
#define BB   4
#define TT   1024
#define DD   1024
#define HH   16
#define HD   64
#define D3   3072   // 3*D
#define MTOT 4096   // B*T

// Scratch (allocation-free rule: __device__ globals)
__device__ float g_qkv[(size_t)BB * TT * D3];     // 48 MB: [b*T+t][3D]
__device__ float g_att[(size_t)BB * TT * DD];     // 16 MB: [b*T+t][D]
__device__ float g_wqkvT[(size_t)D3 * DD];        // 12 MB: w_qkv^T [3D][D]
__device__ float g_woutT[(size_t)DD * DD];        //  4 MB: w_out^T [D][D]

// ============================================================================
// Helpers (baseline PTX only — no sm_103a-suffix features; the harness
// compiles through compute_103 which rejects tcgen05/TMEM)
// ============================================================================
__device__ __forceinline__ uint32_t smem_u32(const void* p) {
    uint32_t a;
    asm("{ .reg .u64 t; cvta.to.shared.u64 t, %1; cvt.u32.u64 %0, t; }"
        : "=r"(a) : "l"(p));
    return a;
}
__device__ __forceinline__ float to_tf32(float x) {
    float r;
    asm("cvt.rna.tf32.f32 %0, %1;" : "=f"(r) : "f"(x));
    return r;
}
#define CP_ASYNC16(dst, src) \
    asm volatile("cp.async.cg.shared.global [%0], [%1], 16;" \
                 :: "r"(dst), "l"(src) : "memory")
#define CP_COMMIT() asm volatile("cp.async.commit_group;" ::: "memory")
#define CP_WAIT1()  asm volatile("cp.async.wait_group 1;"  ::: "memory")

__device__ __forceinline__ void mma_tf32(float* c, const uint32_t* a,
                                         const uint32_t* b) {
    asm volatile(
        "mma.sync.aligned.m16n8k8.row.col.f32.tf32.tf32.f32 "
        "{%0,%1,%2,%3}, {%4,%5,%6,%7}, {%8,%9}, {%0,%1,%2,%3};"
        : "+f"(c[0]), "+f"(c[1]), "+f"(c[2]), "+f"(c[3])
        : "r"(a[0]), "r"(a[1]), "r"(a[2]), "r"(a[3]), "r"(b[0]), "r"(b[1]));
}

// ============================================================================
// Weight transpose: src [R][C] row-major -> dst [C][R] row-major
// ============================================================================
__global__ __launch_bounds__(256)
void transpose32(const float* __restrict__ src, float* __restrict__ dst,
                 int R, int C)
{
    __shared__ float t[32][33];
    const int bx = blockIdx.x * 32;
    const int by = blockIdx.y * 32;
    const int lx = threadIdx.x & 31;
    const int ly = threadIdx.x >> 5;
#pragma unroll
    for (int i = 0; i < 32; i += 8)
        t[ly + i][lx] = src[(size_t)(by + ly + i) * C + bx + lx];
    __syncthreads();
#pragma unroll
    for (int i = 0; i < 32; i += 8)
        dst[(size_t)(bx + ly + i) * R + by + lx] = t[lx][ly + i];
}

// ============================================================================
// tf32 mma.sync GEMM: C[M,N] = A[M,K] @ Bt[N,K]^T  (both operands K-major).
// BM=BN=128, BK=16, 256 thr = 8 warps (2x4), warp tile 64x32.
// SMEM rows padded to pitch 20 floats (conflict-free for the m16n8k8
// fragment pattern). 3-stage cp.async pipeline, fp32 accum in registers.
// ============================================================================
#define PITCH  20                      // floats per SMEM row (16 data + 4 pad)
#define STAGEB (128 * PITCH * 4)       // bytes per operand per stage = 10240
#define NSTAGE 3
#define GEMM_SMEM (NSTAGE * 2 * STAGEB)   // 61440 B

__global__ __launch_bounds__(256)
void mma_gemm(const float* __restrict__ A, const float* __restrict__ Bt,
              float* __restrict__ C, int M, int N, int K)
{
    extern __shared__ float smf[];
    const uint32_t smem_base = smem_u32(smf);

    const int tid    = threadIdx.x;
    const int lane   = tid & 31;
    const int wid    = tid >> 5;
    const int warp_m = wid >> 2;       // 0..1 -> m offset *64
    const int warp_n = wid & 3;        // 0..3 -> n offset *32

    const int m0 = blockIdx.y * 128;
    const int n0 = blockIdx.x * 128;

    // Per-thread cp.async geometry: row = tid>>1 (0..127), q = tid&1 (8 floats)
    const int lrow = tid >> 1;
    const int q    = tid & 1;
    const float* ag = A  + (size_t)(m0 + lrow) * K + q * 8;
    const float* bg = Bt + (size_t)(n0 + lrow) * K + q * 8;
    const uint32_t sdA = smem_base + lrow * (PITCH * 4) + q * 32;

    float acc[4][4][4];
#pragma unroll
    for (int i = 0; i < 4; i++)
#pragma unroll
        for (int j = 0; j < 4; j++)
#pragma unroll
            for (int r = 0; r < 4; r++) acc[i][j][r] = 0.0f;

    const int nchunks = K >> 4;        // 64 for K=1024

    // Prologue: issue stages 0..NSTAGE-2
#pragma unroll
    for (int s = 0; s < NSTAGE - 1; ++s) {
        const uint32_t aD = sdA + s * (2 * STAGEB);
        const uint32_t bD = aD + STAGEB;
        CP_ASYNC16(aD,      ag + s * 16);
        CP_ASYNC16(aD + 16, ag + s * 16 + 4);
        CP_ASYNC16(bD,      bg + s * 16);
        CP_ASYNC16(bD + 16, bg + s * 16 + 4);
        CP_COMMIT();
    }

    const int frow  = lane >> 2;       // 0..7
    const int fcol  = lane & 3;        // 0..3
    const int arow0 = warp_m * 64;
    const int brow0 = warp_n * 32;

    for (int c = 0; c < nchunks; ++c) {
        CP_WAIT1();
        __syncthreads();

        const int   st  = c % NSTAGE;
        const float* As = smf + st * (2 * STAGEB / 4);
        const float* Bs = As + (STAGEB / 4);

#pragma unroll
        for (int kk = 0; kk < 16; kk += 8) {
            // Load fragments (tf32-rounded)
            uint32_t af[4][4];
#pragma unroll
            for (int mt = 0; mt < 4; mt++) {
                const int r = arow0 + mt * 16 + frow;
                const float* p0 = As + r * PITCH + kk + fcol;
                const float* p1 = p0 + 8 * PITCH;
                af[mt][0] = __float_as_uint(to_tf32(p0[0]));
                af[mt][1] = __float_as_uint(to_tf32(p1[0]));
                af[mt][2] = __float_as_uint(to_tf32(p0[4]));
                af[mt][3] = __float_as_uint(to_tf32(p1[4]));
            }
            uint32_t bf[4][2];
#pragma unroll
            for (int nt = 0; nt < 4; nt++) {
                const int r = brow0 + nt * 8 + frow;
                const float* p = Bs + r * PITCH + kk + fcol;
                bf[nt][0] = __float_as_uint(to_tf32(p[0]));
                bf[nt][1] = __float_as_uint(to_tf32(p[4]));
            }
#pragma unroll
            for (int mt = 0; mt < 4; mt++)
#pragma unroll
                for (int nt = 0; nt < 4; nt++)
                    mma_tf32(acc[mt][nt], af[mt], bf[nt]);
        }

        // Issue chunk c + NSTAGE - 1 into stage it maps to (empty commit ok)
        const int nc = c + NSTAGE - 1;
        if (nc < nchunks) {
            const int s = nc % NSTAGE;
            const uint32_t aD = sdA + s * (2 * STAGEB);
            const uint32_t bD = aD + STAGEB;
            CP_ASYNC16(aD,      ag + nc * 16);
            CP_ASYNC16(aD + 16, ag + nc * 16 + 4);
            CP_ASYNC16(bD,      bg + nc * 16);
            CP_ASYNC16(bD + 16, bg + nc * 16 + 4);
        }
        CP_COMMIT();
    }

    // Epilogue: c-fragment layout -> float2 stores
    const int crow = lane >> 2;
    const int ccol = (lane & 3) * 2;
#pragma unroll
    for (int mt = 0; mt < 4; mt++) {
        const int rbase = m0 + warp_m * 64 + mt * 16 + crow;
#pragma unroll
        for (int nt = 0; nt < 4; nt++) {
            const int cbase = n0 + warp_n * 32 + nt * 8 + ccol;
            *reinterpret_cast<float2*>(C + (size_t)rbase * N + cbase) =
                make_float2(acc[mt][nt][0], acc[mt][nt][1]);
            *reinterpret_cast<float2*>(C + (size_t)(rbase + 8) * N + cbase) =
                make_float2(acc[mt][nt][2], acc[mt][nt][3]);
        }
    }
}

// ---------------------------------------------------------------------------
// Flash attention (causal), fp32, register-blocked (unchanged — validated).
// ---------------------------------------------------------------------------
#define QP 132
#define KP 68
#define ATT2_SMEM ((64 * QP + 64 * KP + 64 * KP + 64 * QP) * 4)  // 102400 B

__global__ __launch_bounds__(256, 2)
void attn128(const float* __restrict__ qkv, float* __restrict__ att)
{
    extern __shared__ float sm[];
    float* Qs = sm;                     // [64][QP]  d-major
    float* Ks = Qs + 64 * QP;           // [64][KP]  d-major
    float* Vs = Ks + 64 * KP;           // [64][KP]  key-major
    float* Ps = Vs + 64 * KP;           // [64][QP]  key-major

    const int tid = threadIdx.x;
    const int tr  = tid >> 4;
    const int tc  = tid & 15;
    const int r0  = tr * 8;
    const int c0  = tc * 4;

    const int bh  = blockIdx.y;
    const int b   = bh >> 4;
    const int h   = bh & 15;
    const int bxe = (int)(gridDim.x - 1) - (int)blockIdx.x;  // heavy first
    const int q0  = bxe * 128;

    const float* base = qkv + (size_t)b * TT * D3 + h * HD;

    {
        const int lr    = tid >> 1;
        const int dbase = (tid & 1) * 32;
        const float* g  = base + (size_t)(q0 + lr) * D3 + dbase;
#pragma unroll
        for (int i = 0; i < 8; i++) {
            float4 v = reinterpret_cast<const float4*>(g)[i];
            const int d = dbase + i * 4;
            Qs[(d + 0) * QP + lr] = v.x * 0.125f;
            Qs[(d + 1) * QP + lr] = v.y * 0.125f;
            Qs[(d + 2) * QP + lr] = v.z * 0.125f;
            Qs[(d + 3) * QP + lr] = v.w * 0.125f;
        }
    }

    float o[8][4];
#pragma unroll
    for (int i = 0; i < 8; i++)
#pragma unroll
        for (int j = 0; j < 4; j++) o[i][j] = 0.0f;
    float mrow[8], lrow[8];
#pragma unroll
    for (int i = 0; i < 8; i++) { mrow[i] = -INFINITY; lrow[i] = 0.0f; }

    const int ntiles = 2 * bxe + 2;

    for (int kt = 0; kt < ntiles; ++kt) {
        __syncthreads();
        {
            const int kr    = tid >> 2;
            const int dbase = (tid & 3) * 16;
            const float* kg = base + 1024 + (size_t)(kt * 64 + kr) * D3 + dbase;
            const float* vg = kg + 1024;
#pragma unroll
            for (int i = 0; i < 4; i++) {
                float4 kv = reinterpret_cast<const float4*>(kg)[i];
                const int d = dbase + i * 4;
                Ks[(d + 0) * KP + kr] = kv.x;
                Ks[(d + 1) * KP + kr] = kv.y;
                Ks[(d + 2) * KP + kr] = kv.z;
                Ks[(d + 3) * KP + kr] = kv.w;
                *reinterpret_cast<float4*>(&Vs[kr * KP + d]) =
                    reinterpret_cast<const float4*>(vg)[i];
            }
        }
        __syncthreads();

        float s[8][4];
#pragma unroll
        for (int i = 0; i < 8; i++)
#pragma unroll
            for (int j = 0; j < 4; j++) s[i][j] = 0.0f;

#pragma unroll 4
        for (int d = 0; d < 64; ++d) {
            float ra[8], rb[4];
            *reinterpret_cast<float4*>(ra)     = *reinterpret_cast<const float4*>(&Qs[d * QP + r0]);
            *reinterpret_cast<float4*>(ra + 4) = *reinterpret_cast<const float4*>(&Qs[d * QP + r0 + 4]);
            *reinterpret_cast<float4*>(rb)     = *reinterpret_cast<const float4*>(&Ks[d * KP + c0]);
#pragma unroll
            for (int i = 0; i < 8; i++)
#pragma unroll
                for (int j = 0; j < 4; j++)
                    s[i][j] = fmaf(ra[i], rb[j], s[i][j]);
        }

        const int dk = kt - 2 * bxe;
        if (dk >= 0) {
#pragma unroll
            for (int i = 0; i < 8; i++)
#pragma unroll
                for (int j = 0; j < 4; j++)
                    if (dk * 64 + c0 + j > r0 + i) s[i][j] = -INFINITY;
        }

#pragma unroll
        for (int i = 0; i < 8; i++) {
            float mt = fmaxf(fmaxf(s[i][0], s[i][1]), fmaxf(s[i][2], s[i][3]));
            mt = fmaxf(mt, __shfl_xor_sync(0xffffffffu, mt, 1));
            mt = fmaxf(mt, __shfl_xor_sync(0xffffffffu, mt, 2));
            mt = fmaxf(mt, __shfl_xor_sync(0xffffffffu, mt, 4));
            mt = fmaxf(mt, __shfl_xor_sync(0xffffffffu, mt, 8));

            const float mn   = fmaxf(mrow[i], mt);
            const float corr = __expf(mrow[i] - mn);
            float ls = 0.0f;
#pragma unroll
            for (int j = 0; j < 4; j++) {
                const float p = __expf(s[i][j] - mn);
                s[i][j] = p;
                ls += p;
            }
            ls += __shfl_xor_sync(0xffffffffu, ls, 1);
            ls += __shfl_xor_sync(0xffffffffu, ls, 2);
            ls += __shfl_xor_sync(0xffffffffu, ls, 4);
            ls += __shfl_xor_sync(0xffffffffu, ls, 8);
            lrow[i] = lrow[i] * corr + ls;
            mrow[i] = mn;
            o[i][0] *= corr; o[i][1] *= corr; o[i][2] *= corr; o[i][3] *= corr;
        }

#pragma unroll
        for (int j = 0; j < 4; j++) {
            float4 lo = make_float4(s[0][j], s[1][j], s[2][j], s[3][j]);
            float4 hi = make_float4(s[4][j], s[5][j], s[6][j], s[7][j]);
            *reinterpret_cast<float4*>(&Ps[(c0 + j) * QP + r0])     = lo;
            *reinterpret_cast<float4*>(&Ps[(c0 + j) * QP + r0 + 4]) = hi;
        }
        __syncthreads();

#pragma unroll 4
        for (int k = 0; k < 64; ++k) {
            float pa[8], vb[4];
            *reinterpret_cast<float4*>(pa)     = *reinterpret_cast<const float4*>(&Ps[k * QP + r0]);
            *reinterpret_cast<float4*>(pa + 4) = *reinterpret_cast<const float4*>(&Ps[k * QP + r0 + 4]);
            *reinterpret_cast<float4*>(vb)     = *reinterpret_cast<const float4*>(&Vs[k * KP + c0]);
#pragma unroll
            for (int i = 0; i < 8; i++)
#pragma unroll
                for (int j = 0; j < 4; j++)
                    o[i][j] = fmaf(pa[i], vb[j], o[i][j]);
        }
    }

#pragma unroll
    for (int i = 0; i < 8; i++) {
        const float inv = 1.0f / lrow[i];
        float* op = att + (size_t)(b * TT + q0 + r0 + i) * DD + h * HD + c0;
        *reinterpret_cast<float4*>(op) =
            make_float4(o[i][0] * inv, o[i][1] * inv, o[i][2] * inv, o[i][3] * inv);
    }
}

// ---------------------------------------------------------------------------
// Launch (graph-capturable): transpose weights -> mma QKV GEMM -> flash attn
// -> mma output GEMM. Inputs: x[f32], mask[i32, ignored: exactly triu(k=1)],
// w_qkv[f32], w_out[f32]. Output f32 [B,T,D].
// ---------------------------------------------------------------------------
extern "C" void kernel_launch(void* const* d_in, const int* in_sizes, int n_in,
                              void* d_out, int out_size)
{
    const float* x     = (const float*)d_in[0];
    const float* w_qkv = (const float*)d_in[2];
    const float* w_out = (const float*)d_in[3];
    float*       out   = (float*)d_out;

    float *qkv_p = nullptr, *att_p = nullptr, *wqkvT = nullptr, *woutT = nullptr;
    cudaGetSymbolAddress((void**)&qkv_p, g_qkv);
    cudaGetSymbolAddress((void**)&att_p, g_att);
    cudaGetSymbolAddress((void**)&wqkvT, g_wqkvT);
    cudaGetSymbolAddress((void**)&woutT, g_woutT);

    cudaFuncSetAttribute(attn128,
                         cudaFuncAttributeMaxDynamicSharedMemorySize, ATT2_SMEM);
    cudaFuncSetAttribute(mma_gemm,
                         cudaFuncAttributeMaxDynamicSharedMemorySize, GEMM_SMEM);

    // 0) transpose weights to [N][K] for K-major tensor-core loads
    transpose32<<<dim3(D3 / 32, DD / 32), 256>>>(w_qkv, wqkvT, DD, D3);
    transpose32<<<dim3(DD / 32, DD / 32), 256>>>(w_out, woutT, DD, DD);

    // 1) qkv = x @ w_qkv : [4096,1024] @ [1024,3072]  (tf32 mma.sync)
    mma_gemm<<<dim3(D3 / 128, MTOT / 128), 256, GEMM_SMEM>>>(x, wqkvT, qkv_p,
                                                             MTOT, D3, DD);

    // 2) causal flash attention: 8 q-blocks x 64 (b,h) pairs
    attn128<<<dim3(TT / 128, BB * HH), 256, ATT2_SMEM>>>(qkv_p, att_p);

    // 3) out = att @ w_out : [4096,1024] @ [1024,1024]  (tf32 mma.sync)
    mma_gemm<<<dim3(DD / 128, MTOT / 128), 256, GEMM_SMEM>>>(att_p, woutT, out,
                                                             MTOT, DD, DD);
}

// round 14
// speedup vs baseline: 5.5876x; 1.4271x over previous
#include <cuda_runtime.h>
#include <cuda_bf16.h>
#include <math.h>
#include <stdint.h>

// Problem constants
#define BB   4
#define TT   1024
#define DD   1024
#define HH   16
#define HD   64
#define D3   3072   // 3*D
#define MTOT 4096   // B*T

// Scratch (allocation-free rule: __device__ globals)
__device__ float g_qkv[(size_t)BB * TT * D3];     // 48 MB: [b*T+t][3D]
__device__ float g_att[(size_t)BB * TT * DD];     // 16 MB: [b*T+t][D]
__device__ float g_wqkvT[(size_t)D3 * DD];        // 12 MB: w_qkv^T [3D][D]
__device__ float g_woutT[(size_t)DD * DD];        //  4 MB: w_out^T [D][D]

// ============================================================================
// Helpers (baseline PTX only — compute_103 rejects tcgen05/TMEM; tf32
// mma.sync + cp.async are the validated tensor-core path on this toolchain)
// ============================================================================
__device__ __forceinline__ uint32_t smem_u32(const void* p) {
    uint32_t a;
    asm("{ .reg .u64 t; cvta.to.shared.u64 t, %1; cvt.u32.u64 %0, t; }"
        : "=r"(a) : "l"(p));
    return a;
}
__device__ __forceinline__ float to_tf32(float x) {
    float r;
    asm("cvt.rna.tf32.f32 %0, %1;" : "=f"(r) : "f"(x));
    return r;
}
#define CP_ASYNC16(dst, src) \
    asm volatile("cp.async.cg.shared.global [%0], [%1], 16;" \
                 :: "r"(dst), "l"(src) : "memory")
#define CP_COMMIT() asm volatile("cp.async.commit_group;" ::: "memory")
#define CP_WAIT1()  asm volatile("cp.async.wait_group 1;"  ::: "memory")

__device__ __forceinline__ void mma_tf32(float* c, const uint32_t* a,
                                         const uint32_t* b) {
    asm volatile(
        "mma.sync.aligned.m16n8k8.row.col.f32.tf32.tf32.f32 "
        "{%0,%1,%2,%3}, {%4,%5,%6,%7}, {%8,%9}, {%0,%1,%2,%3};"
        : "+f"(c[0]), "+f"(c[1]), "+f"(c[2]), "+f"(c[3])
        : "r"(a[0]), "r"(a[1]), "r"(a[2]), "r"(a[3]), "r"(b[0]), "r"(b[1]));
}

// ============================================================================
// Weight transpose: src [R][C] row-major -> dst [C][R] row-major
// ============================================================================
__global__ __launch_bounds__(256)
void transpose32(const float* __restrict__ src, float* __restrict__ dst,
                 int R, int C)
{
    __shared__ float t[32][33];
    const int bx = blockIdx.x * 32;
    const int by = blockIdx.y * 32;
    const int lx = threadIdx.x & 31;
    const int ly = threadIdx.x >> 5;
#pragma unroll
    for (int i = 0; i < 32; i += 8)
        t[ly + i][lx] = src[(size_t)(by + ly + i) * C + bx + lx];
    __syncthreads();
#pragma unroll
    for (int i = 0; i < 32; i += 8)
        dst[(size_t)(bx + ly + i) * R + by + lx] = t[lx][ly + i];
}

// ============================================================================
// tf32 mma.sync GEMM (unchanged, validated R12): C = A[M,K] @ Bt[N,K]^T
// ============================================================================
#define PITCH  20
#define STAGEB (128 * PITCH * 4)
#define NSTAGE 3
#define GEMM_SMEM (NSTAGE * 2 * STAGEB)   // 61440 B

__global__ __launch_bounds__(256)
void mma_gemm(const float* __restrict__ A, const float* __restrict__ Bt,
              float* __restrict__ C, int M, int N, int K)
{
    extern __shared__ float smf[];
    const uint32_t smem_base = smem_u32(smf);

    const int tid    = threadIdx.x;
    const int lane   = tid & 31;
    const int wid    = tid >> 5;
    const int warp_m = wid >> 2;
    const int warp_n = wid & 3;

    const int m0 = blockIdx.y * 128;
    const int n0 = blockIdx.x * 128;

    const int lrow = tid >> 1;
    const int q    = tid & 1;
    const float* ag = A  + (size_t)(m0 + lrow) * K + q * 8;
    const float* bg = Bt + (size_t)(n0 + lrow) * K + q * 8;
    const uint32_t sdA = smem_base + lrow * (PITCH * 4) + q * 32;

    float acc[4][4][4];
#pragma unroll
    for (int i = 0; i < 4; i++)
#pragma unroll
        for (int j = 0; j < 4; j++)
#pragma unroll
            for (int r = 0; r < 4; r++) acc[i][j][r] = 0.0f;

    const int nchunks = K >> 4;

#pragma unroll
    for (int s = 0; s < NSTAGE - 1; ++s) {
        const uint32_t aD = sdA + s * (2 * STAGEB);
        const uint32_t bD = aD + STAGEB;
        CP_ASYNC16(aD,      ag + s * 16);
        CP_ASYNC16(aD + 16, ag + s * 16 + 4);
        CP_ASYNC16(bD,      bg + s * 16);
        CP_ASYNC16(bD + 16, bg + s * 16 + 4);
        CP_COMMIT();
    }

    const int frow  = lane >> 2;
    const int fcol  = lane & 3;
    const int arow0 = warp_m * 64;
    const int brow0 = warp_n * 32;

    for (int c = 0; c < nchunks; ++c) {
        CP_WAIT1();
        __syncthreads();

        const int   st  = c % NSTAGE;
        const float* As = smf + st * (2 * STAGEB / 4);
        const float* Bs = As + (STAGEB / 4);

#pragma unroll
        for (int kk = 0; kk < 16; kk += 8) {
            uint32_t af[4][4];
#pragma unroll
            for (int mt = 0; mt < 4; mt++) {
                const int r = arow0 + mt * 16 + frow;
                const float* p0 = As + r * PITCH + kk + fcol;
                const float* p1 = p0 + 8 * PITCH;
                af[mt][0] = __float_as_uint(to_tf32(p0[0]));
                af[mt][1] = __float_as_uint(to_tf32(p1[0]));
                af[mt][2] = __float_as_uint(to_tf32(p0[4]));
                af[mt][3] = __float_as_uint(to_tf32(p1[4]));
            }
            uint32_t bf[4][2];
#pragma unroll
            for (int nt = 0; nt < 4; nt++) {
                const int r = brow0 + nt * 8 + frow;
                const float* p = Bs + r * PITCH + kk + fcol;
                bf[nt][0] = __float_as_uint(to_tf32(p[0]));
                bf[nt][1] = __float_as_uint(to_tf32(p[4]));
            }
#pragma unroll
            for (int mt = 0; mt < 4; mt++)
#pragma unroll
                for (int nt = 0; nt < 4; nt++)
                    mma_tf32(acc[mt][nt], af[mt], bf[nt]);
        }

        const int nc = c + NSTAGE - 1;
        if (nc < nchunks) {
            const int s = nc % NSTAGE;
            const uint32_t aD = sdA + s * (2 * STAGEB);
            const uint32_t bD = aD + STAGEB;
            CP_ASYNC16(aD,      ag + nc * 16);
            CP_ASYNC16(aD + 16, ag + nc * 16 + 4);
            CP_ASYNC16(bD,      bg + nc * 16);
            CP_ASYNC16(bD + 16, bg + nc * 16 + 4);
        }
        CP_COMMIT();
    }

    const int crow = lane >> 2;
    const int ccol = (lane & 3) * 2;
#pragma unroll
    for (int mt = 0; mt < 4; mt++) {
        const int rbase = m0 + warp_m * 64 + mt * 16 + crow;
#pragma unroll
        for (int nt = 0; nt < 4; nt++) {
            const int cbase = n0 + warp_n * 32 + nt * 8 + ccol;
            *reinterpret_cast<float2*>(C + (size_t)rbase * N + cbase) =
                make_float2(acc[mt][nt][0], acc[mt][nt][1]);
            *reinterpret_cast<float2*>(C + (size_t)(rbase + 8) * N + cbase) =
                make_float2(acc[mt][nt][2], acc[mt][nt][3]);
        }
    }
}

// ============================================================================
// Flash attention (causal) on tf32 mma.sync.
// CTA = 128 queries x one (b,h); KV tiles of 64; 8 warps x m16 rows each.
// Each warp computes its full S row-block (16x64) and O (16x64).
// Pitch-68 layouts make ALL fragment LDS conflict-free:
//   Qs[q][d], Ks[kv][d], Vt[d][kv], Ps[q][kv] — bank = 4*(lane>>2)+(lane&3).
// Softmax row stats live in the quad (shfl_xor 1,2). P goes through
// warp-private SMEM (__syncwarp only) to bridge C-frag -> A-frag layouts.
// ============================================================================
#define AP 68
#define QS_OFF 0
#define KS_OFF (128 * AP)                  // 8704
#define VT_OFF (KS_OFF + 64 * AP)          // 13056
#define PS_OFF (VT_OFF + 64 * AP)          // 17408
#define ATTM_SMEM ((PS_OFF + 128 * AP) * 4)   // 104448 B

__global__ __launch_bounds__(256, 2)
void attn_mma(const float* __restrict__ qkv, float* __restrict__ att)
{
    extern __shared__ float sm[];
    float* Qs = sm + QS_OFF;
    float* Ks = sm + KS_OFF;
    float* Vt = sm + VT_OFF;
    float* Ps = sm + PS_OFF;

    const int tid  = threadIdx.x;
    const int lane = tid & 31;
    const int wid  = tid >> 5;
    const int g    = lane >> 2;        // fragment group row 0..7
    const int t    = lane & 3;         // thread-in-group 0..3
    const int wq0  = wid * 16;         // warp's query-row block

    const int bh  = blockIdx.y;
    const int b   = bh >> 4;
    const int h   = bh & 15;
    const int bxe = (int)(gridDim.x - 1) - (int)blockIdx.x;  // heavy first
    const int q0  = bxe * 128;

    const float* base = qkv + (size_t)b * TT * D3 + h * HD;

    // ---- Q fill: rows q0..q0+127, scaled by 0.125 and tf32-rounded ----
    {
        const int lr = tid >> 1;
        const int d0 = (tid & 1) * 32;
        const float4* gq = reinterpret_cast<const float4*>(
            base + (size_t)(q0 + lr) * D3 + d0);
#pragma unroll
        for (int i = 0; i < 8; i++) {
            float4 v = gq[i];
            v.x = to_tf32(v.x * 0.125f); v.y = to_tf32(v.y * 0.125f);
            v.z = to_tf32(v.z * 0.125f); v.w = to_tf32(v.w * 0.125f);
            *reinterpret_cast<float4*>(&Qs[lr * AP + d0 + i * 4]) = v;
        }
    }

    float oacc[8][4];
#pragma unroll
    for (int i = 0; i < 8; i++)
#pragma unroll
        for (int j = 0; j < 4; j++) oacc[i][j] = 0.0f;
    float m0 = -INFINITY, m1 = -INFINITY, l0 = 0.0f, l1 = 0.0f;

    const int ntiles = 2 * bxe + 2;

    for (int kt = 0; kt < ntiles; ++kt) {
        __syncthreads();   // all warps done reading Ks/Vt of prior tile

        // ---- K/V tile fill (tf32-rounded); V stored transposed ----
        {
            const int kr = tid >> 2;
            const int db = (tid & 3) * 16;
            const float4* kg = reinterpret_cast<const float4*>(
                base + 1024 + (size_t)(kt * 64 + kr) * D3 + db);
            const float4* vg = reinterpret_cast<const float4*>(
                base + 2048 + (size_t)(kt * 64 + kr) * D3 + db);
#pragma unroll
            for (int i = 0; i < 4; i++) {
                float4 kv = kg[i];
                kv.x = to_tf32(kv.x); kv.y = to_tf32(kv.y);
                kv.z = to_tf32(kv.z); kv.w = to_tf32(kv.w);
                *reinterpret_cast<float4*>(&Ks[kr * AP + db + i * 4]) = kv;

                float4 vv = vg[i];
                const int d = db + i * 4;
                Vt[(d + 0) * AP + kr] = to_tf32(vv.x);
                Vt[(d + 1) * AP + kr] = to_tf32(vv.y);
                Vt[(d + 2) * AP + kr] = to_tf32(vv.z);
                Vt[(d + 3) * AP + kr] = to_tf32(vv.w);
            }
        }
        __syncthreads();

        // ---- S = (Q/8) @ K^T : warp block 16 x 64, 8 n-tiles ----
        float sacc[8][4];
#pragma unroll
        for (int nt = 0; nt < 8; nt++)
#pragma unroll
            for (int j = 0; j < 4; j++) sacc[nt][j] = 0.0f;

        const uint32_t* Qr0 = reinterpret_cast<const uint32_t*>(&Qs[(wq0 + g) * AP]);
        const uint32_t* Qr8 = Qr0 + 8 * AP;
#pragma unroll
        for (int ks = 0; ks < 8; ++ks) {
            const int c = ks * 8 + t;
            uint32_t a[4] = { Qr0[c], Qr8[c], Qr0[c + 4], Qr8[c + 4] };
#pragma unroll
            for (int nt = 0; nt < 8; nt++) {
                const uint32_t* Kr =
                    reinterpret_cast<const uint32_t*>(&Ks[(nt * 8 + g) * AP]);
                uint32_t bf[2] = { Kr[c], Kr[c + 4] };
                mma_tf32(sacc[nt], a, bf);
            }
        }

        // ---- causal mask (diagonal region: dk in {0,1}) ----
        const int dk = kt - 2 * bxe;
        if (dk >= 0) {
            const int lr0 = wq0 + g;       // local query row (row+8 = lr0+8)
#pragma unroll
            for (int nt = 0; nt < 8; nt++) {
                const int lc = dk * 64 + nt * 8 + 2 * t;
                if (lc     > lr0)     sacc[nt][0] = -INFINITY;
                if (lc + 1 > lr0)     sacc[nt][1] = -INFINITY;
                if (lc     > lr0 + 8) sacc[nt][2] = -INFINITY;
                if (lc + 1 > lr0 + 8) sacc[nt][3] = -INFINITY;
            }
        }

        // ---- online softmax (rows live in the quad) ----
        float mt0 = -INFINITY, mt1 = -INFINITY;
#pragma unroll
        for (int nt = 0; nt < 8; nt++) {
            mt0 = fmaxf(mt0, fmaxf(sacc[nt][0], sacc[nt][1]));
            mt1 = fmaxf(mt1, fmaxf(sacc[nt][2], sacc[nt][3]));
        }
        mt0 = fmaxf(mt0, __shfl_xor_sync(0xffffffffu, mt0, 1));
        mt0 = fmaxf(mt0, __shfl_xor_sync(0xffffffffu, mt0, 2));
        mt1 = fmaxf(mt1, __shfl_xor_sync(0xffffffffu, mt1, 1));
        mt1 = fmaxf(mt1, __shfl_xor_sync(0xffffffffu, mt1, 2));

        const float mn0 = fmaxf(m0, mt0);
        const float mn1 = fmaxf(m1, mt1);
        const float cr0 = __expf(m0 - mn0);
        const float cr1 = __expf(m1 - mn1);
        float ls0 = 0.0f, ls1 = 0.0f;
#pragma unroll
        for (int nt = 0; nt < 8; nt++) {
            sacc[nt][0] = __expf(sacc[nt][0] - mn0);
            sacc[nt][1] = __expf(sacc[nt][1] - mn0);
            sacc[nt][2] = __expf(sacc[nt][2] - mn1);
            sacc[nt][3] = __expf(sacc[nt][3] - mn1);
            ls0 += sacc[nt][0] + sacc[nt][1];
            ls1 += sacc[nt][2] + sacc[nt][3];
        }
        ls0 += __shfl_xor_sync(0xffffffffu, ls0, 1);
        ls0 += __shfl_xor_sync(0xffffffffu, ls0, 2);
        ls1 += __shfl_xor_sync(0xffffffffu, ls1, 1);
        ls1 += __shfl_xor_sync(0xffffffffu, ls1, 2);
        l0 = l0 * cr0 + ls0;  m0 = mn0;
        l1 = l1 * cr1 + ls1;  m1 = mn1;
#pragma unroll
        for (int dt = 0; dt < 8; dt++) {
            oacc[dt][0] *= cr0; oacc[dt][1] *= cr0;
            oacc[dt][2] *= cr1; oacc[dt][3] *= cr1;
        }

        // ---- P (tf32) to warp-private SMEM rows ----
        {
            float* Pr0 = &Ps[(wq0 + g) * AP];
            float* Pr8 = Pr0 + 8 * AP;
#pragma unroll
            for (int nt = 0; nt < 8; nt++) {
                const int col = nt * 8 + 2 * t;
                *reinterpret_cast<float2*>(Pr0 + col) =
                    make_float2(to_tf32(sacc[nt][0]), to_tf32(sacc[nt][1]));
                *reinterpret_cast<float2*>(Pr8 + col) =
                    make_float2(to_tf32(sacc[nt][2]), to_tf32(sacc[nt][3]));
            }
        }
        __syncwarp();

        // ---- O += P @ V : 8 d-tiles ----
        const uint32_t* Pr0 = reinterpret_cast<const uint32_t*>(&Ps[(wq0 + g) * AP]);
        const uint32_t* Pr8 = Pr0 + 8 * AP;
#pragma unroll
        for (int ks = 0; ks < 8; ++ks) {
            const int c = ks * 8 + t;
            uint32_t a[4] = { Pr0[c], Pr8[c], Pr0[c + 4], Pr8[c + 4] };
#pragma unroll
            for (int dt = 0; dt < 8; dt++) {
                const uint32_t* Vr =
                    reinterpret_cast<const uint32_t*>(&Vt[(dt * 8 + g) * AP]);
                uint32_t bf[2] = { Vr[c], Vr[c + 4] };
                mma_tf32(oacc[dt], a, bf);
            }
        }
    }

    // ---- normalize + store: row = b*T + q0 + wq0 + g (+8), col = h*64+... ----
    const float inv0 = 1.0f / l0;
    const float inv1 = 1.0f / l1;
    float* orow0 = att + (size_t)(b * TT + q0 + wq0 + g) * DD + h * HD;
    float* orow8 = orow0 + (size_t)8 * DD;
#pragma unroll
    for (int dt = 0; dt < 8; dt++) {
        const int col = dt * 8 + 2 * t;
        *reinterpret_cast<float2*>(orow0 + col) =
            make_float2(oacc[dt][0] * inv0, oacc[dt][1] * inv0);
        *reinterpret_cast<float2*>(orow8 + col) =
            make_float2(oacc[dt][2] * inv1, oacc[dt][3] * inv1);
    }
}

// ---------------------------------------------------------------------------
// Launch (graph-capturable): transpose weights -> mma QKV GEMM -> mma attn
// -> mma output GEMM. Inputs: x[f32], mask[i32, ignored: exactly triu(k=1)],
// w_qkv[f32], w_out[f32]. Output f32 [B,T,D].
// ---------------------------------------------------------------------------
extern "C" void kernel_launch(void* const* d_in, const int* in_sizes, int n_in,
                              void* d_out, int out_size)
{
    const float* x     = (const float*)d_in[0];
    const float* w_qkv = (const float*)d_in[2];
    const float* w_out = (const float*)d_in[3];
    float*       out   = (float*)d_out;

    float *qkv_p = nullptr, *att_p = nullptr, *wqkvT = nullptr, *woutT = nullptr;
    cudaGetSymbolAddress((void**)&qkv_p, g_qkv);
    cudaGetSymbolAddress((void**)&att_p, g_att);
    cudaGetSymbolAddress((void**)&wqkvT, g_wqkvT);
    cudaGetSymbolAddress((void**)&woutT, g_woutT);

    cudaFuncSetAttribute(attn_mma,
                         cudaFuncAttributeMaxDynamicSharedMemorySize, ATTM_SMEM);
    cudaFuncSetAttribute(mma_gemm,
                         cudaFuncAttributeMaxDynamicSharedMemorySize, GEMM_SMEM);

    // 0) transpose weights to [N][K] for K-major tensor-core loads
    transpose32<<<dim3(D3 / 32, DD / 32), 256>>>(w_qkv, wqkvT, DD, D3);
    transpose32<<<dim3(DD / 32, DD / 32), 256>>>(w_out, woutT, DD, DD);

    // 1) qkv = x @ w_qkv : [4096,1024] @ [1024,3072]  (tf32 mma.sync)
    mma_gemm<<<dim3(D3 / 128, MTOT / 128), 256, GEMM_SMEM>>>(x, wqkvT, qkv_p,
                                                             MTOT, D3, DD);

    // 2) causal flash attention on tensor cores: 8 q-blocks x 64 (b,h)
    attn_mma<<<dim3(TT / 128, BB * HH), 256, ATTM_SMEM>>>(qkv_p, att_p);

    // 3) out = att @ w_out : [4096,1024] @ [1024,1024]  (tf32 mma.sync)
    mma_gemm<<<dim3(DD / 128, MTOT / 128), 256, GEMM_SMEM>>>(att_p, woutT, out,
                                                             MTOT, DD, DD);
}